// round 17
// baseline (speedup 1.0000x reference)
#include <cuda_runtime.h>
#include <cuda_fp16.h>
#include <cstdint>
#include <math.h>

#define MROWS 4096
#define DMODEL 1024
#define NH 16
#define HD 64
#define QD 16
#define SEQ 2048
#define NBH 32
#define AD 80

// ---------------- scratch ----------------
__device__ __align__(16) float g_Q[MROWS*DMODEL];
__device__ __align__(16) float g_K[MROWS*DMODEL];
__device__ __align__(16) float g_V[MROWS*DMODEL];
__device__ __align__(16) float g_Cq[MROWS*DMODEL];
__device__ __align__(16) float g_Ck[MROWS*DMODEL];
__device__ __align__(16) float g_res[MROWS*DMODEL];
__device__ __align__(16) float g_Va[NBH*SEQ*HD];
__device__ __align__(16) float g_probs_q[MROWS*QD];
__device__ __align__(16) float g_probs_k[MROWS*QD];
__device__ float g_fw_q[MROWS];
__device__ float g_fw_k[MROWS];
__device__ float g_m[NBH*SEQ];
__device__ float g_l[NBH*SEQ];
__device__ float g_M[4*256];

// fp16 buffers (16B-aligned for uint4/cp.async)
__device__ __align__(16) __half g_xh[MROWS*DMODEL];
__device__ __align__(16) __half g_ah[MROWS*DMODEL];
__device__ __align__(16) __half g_Wh[6*DMODEL*DMODEL];     // [widx][n][k]
__device__ __align__(16) __half g_Qah[NBH*SEQ*AD];
__device__ __align__(16) __half g_Kah[NBH*SEQ*AD];
__device__ __align__(16) __half g_Vth[NBH*HD*SEQ];         // [bh][d][s]

// ---------------- helpers ----------------
__device__ __forceinline__ uint32_t smem_u32(const void* p) {
    uint32_t a;
    asm("{ .reg .u64 t; cvta.to.shared.u64 t, %1; cvt.u32.u64 %0, t; }" : "=r"(a) : "l"(p));
    return a;
}
__device__ __forceinline__ void cp16(uint32_t dst, const void* src) {
    asm volatile("cp.async.cg.shared.global [%0], [%1], 16;\n" :: "r"(dst), "l"(src));
}
__device__ __forceinline__ void ldsm4(uint32_t* r, uint32_t addr) {
    asm volatile("ldmatrix.sync.aligned.m8n8.x4.shared.b16 {%0,%1,%2,%3}, [%4];"
        : "=r"(r[0]), "=r"(r[1]), "=r"(r[2]), "=r"(r[3]) : "r"(addr));
}
__device__ __forceinline__ void ldsm2(uint32_t* r, uint32_t addr) {
    asm volatile("ldmatrix.sync.aligned.m8n8.x2.shared.b16 {%0,%1}, [%2];"
        : "=r"(r[0]), "=r"(r[1]) : "r"(addr));
}
__device__ __forceinline__ void mma16816h(float* d, const uint32_t* a, const uint32_t* b) {
    asm volatile("mma.sync.aligned.m16n8k16.row.col.f32.f16.f16.f32 "
        "{%0,%1,%2,%3}, {%4,%5,%6,%7}, {%8,%9}, {%0,%1,%2,%3};"
        : "+f"(d[0]), "+f"(d[1]), "+f"(d[2]), "+f"(d[3])
        : "r"(a[0]), "r"(a[1]), "r"(a[2]), "r"(a[3]), "r"(b[0]), "r"(b[1]));
}
__device__ __forceinline__ void stcs2(float* p, float a, float b) {
    asm volatile("st.global.cs.v2.f32 [%0], {%1, %2};" :: "l"(p), "f"(a), "f"(b) : "memory");
}

// ---------------- conversions ----------------
__global__ __launch_bounds__(256) void aconv_kernel(const float* __restrict__ a,
    __half* __restrict__ h)
{
    size_t i = ((size_t)blockIdx.x * 256 + threadIdx.x) * 8;
    float4 v0 = *(const float4*)&a[i];
    float4 v1 = *(const float4*)&a[i + 4];
    __half2 o[4];
    o[0] = __floats2half2_rn(v0.x, v0.y);
    o[1] = __floats2half2_rn(v0.z, v0.w);
    o[2] = __floats2half2_rn(v1.x, v1.y);
    o[3] = __floats2half2_rn(v1.z, v1.w);
    *(uint4*)&h[i] = *(uint4*)o;
}

struct WconvP { const float* W[6]; };
__global__ __launch_bounds__(256) void wconv6_kernel(WconvP P, __half* __restrict__ h_base)
{
    __shared__ float tile[32][33];
    const float* W = P.W[blockIdx.z];
    __half* hh = h_base + (size_t)blockIdx.z * DMODEL * DMODEL;
    int bx = blockIdx.x * 32;
    int by = blockIdx.y * 32;
    int tx = threadIdx.x, ty = threadIdx.y;
#pragma unroll
    for (int i = 0; i < 32; i += 8)
        tile[ty + i][tx] = W[(size_t)(by + ty + i) * 1024 + bx + tx];
    __syncthreads();
#pragma unroll
    for (int i = 0; i < 32; i += 8) {
        int n = bx + ty + i, k = by + tx;
        hh[(size_t)n * 1024 + k] = __float2half_rn(tile[tx][ty + i]);
    }
}

// ---------------- mma.sync fp16 GEMM (3-stage, 1 sync/iter) ----------------
#define SROW 40
#define MAT_E (128*SROW)
#define SST_B (2*MAT_E*2)          // 20480 per stage
#define GEMM_SMEM (3*SST_B)        // 61440

__device__ __forceinline__ void load_chunk_mm(uint32_t sb, int t, int m0, int n0, int k0,
    const __half* Ah, const __half* Bh)
{
#pragma unroll
    for (int i = 0; i < 2; i++) {
        int cid = i * 256 + t;
        int row = cid >> 2, c = cid & 3;
        uint32_t off = (uint32_t)(row * (SROW*2) + c * 16);
        cp16(sb + off,           (const char*)(Ah + (size_t)(m0 + row) * 1024 + k0) + c * 16);
        cp16(sb + MAT_E*2 + off, (const char*)(Bh + (size_t)(n0 + row) * 1024 + k0) + c * 16);
    }
    asm volatile("cp.async.commit_group;\n" ::: "memory");
}

__device__ __forceinline__ void gemm_body(
    uint32_t sb, int m0, int n0,
    const __half* Ah, const __half* Bh,
    const float* bias, const float* resid, float* out, int do_tanh)
{
    int t = threadIdx.x;
    int warp = t >> 5, lane = t & 31;
    int wm = warp & 1, wn = warp >> 1;

    float acc[4][4][4];
#pragma unroll
    for (int a = 0; a < 4; a++)
#pragma unroll
        for (int b = 0; b < 4; b++)
#pragma unroll
            for (int c = 0; c < 4; c++) acc[a][b][c] = 0.f;

    int aq = lane >> 3;
    int arow = (aq & 1) * 8 + (lane & 7);
    int akoff = (aq >> 1) * 8;
    int brow = lane & 7;
    int bkoff = ((lane >> 3) & 1) * 8;

    load_chunk_mm(sb, t, m0, n0, 0, Ah, Bh);
    load_chunk_mm(sb + SST_B, t, m0, n0, 32, Ah, Bh);

#pragma unroll 1
    for (int c = 0; c < 32; c++) {
        if (c < 31) asm volatile("cp.async.wait_group 1;\n" ::: "memory");
        else        asm volatile("cp.async.wait_group 0;\n" ::: "memory");
        __syncthreads();
        if (c + 2 < 32)
            load_chunk_mm(sb + (uint32_t)(((c + 2) % 3) * SST_B), t, m0, n0, (c + 2) * 32, Ah, Bh);

        uint32_t st = sb + (uint32_t)((c % 3) * SST_B);
#pragma unroll
        for (int k16 = 0; k16 < 2; k16++) {
            int kb = k16 * 16;
            uint32_t ah4[4][4];
#pragma unroll
            for (int mt = 0; mt < 4; mt++) {
                uint32_t aaddr = st + (uint32_t)(((wm*64 + mt*16 + arow) * SROW + kb + akoff) * 2);
                ldsm4(ah4[mt], aaddr);
            }
#pragma unroll
            for (int nt = 0; nt < 4; nt++) {
                uint32_t baddr = st + MAT_E*2 +
                    (uint32_t)(((wn*32 + nt*8 + brow) * SROW + kb + bkoff) * 2);
                uint32_t bh2[2];
                ldsm2(bh2, baddr);
#pragma unroll
                for (int mt = 0; mt < 4; mt++)
                    mma16816h(acc[mt][nt], ah4[mt], bh2);
            }
        }
    }

    int rin = lane >> 2, cin = (lane & 3) * 2;
#pragma unroll
    for (int mt = 0; mt < 4; mt++) {
#pragma unroll
        for (int nt = 0; nt < 4; nt++) {
            int n = n0 + wn*32 + nt*8 + cin;
            float b0 = bias[n], b1 = bias[n + 1];
#pragma unroll
            for (int half_i = 0; half_i < 2; half_i++) {
                int m = m0 + wm*64 + mt*16 + rin + half_i*8;
                float v0 = acc[mt][nt][half_i*2 + 0] + b0;
                float v1 = acc[mt][nt][half_i*2 + 1] + b1;
                if (resid) {
                    const float* rr = resid + (size_t)m * 1024 + n;
                    v0 += rr[0]; v1 += rr[1];
                }
                if (do_tanh) { v0 = tanhf(v0); v1 = tanhf(v1); }
                *(float2*)&out[(size_t)m * 1024 + n] = make_float2(v0, v1);
            }
        }
    }
}

struct GemmP5 {
    const __half* Bh[5];
    const float* bias[5];
    float* out[5];
    int tanh_f[5];
};

__global__ __launch_bounds__(256) void mma_gemm5_kernel(
    const __half* __restrict__ Ah, GemmP5 P)
{
    extern __shared__ char smem[];
    uint32_t sb = smem_u32(smem);
    int z = blockIdx.z;
    gemm_body(sb, blockIdx.x * 128, blockIdx.y * 128,
              Ah, P.Bh[z], P.bias[z], nullptr, P.out[z], P.tanh_f[z]);
}

// ---------------- prep: M = qw @ em ----------------
__global__ void prep_m_kernel(const float* __restrict__ qqr, const float* __restrict__ qqi,
                              const float* __restrict__ qkr, const float* __restrict__ qki,
                              const float* __restrict__ qqem, const float* __restrict__ qkem)
{
    int t = threadIdx.x;
    int u = t >> 4, v = t & 15;
    float a = 0.f, b = 0.f, c = 0.f, d = 0.f;
#pragma unroll
    for (int w = 0; w < 16; w++) {
        float e1 = qqem[w*16+v], e2 = qkem[w*16+v];
        a += qqr[u*16+w]*e1;
        b += qqi[u*16+w]*e1;
        c += qkr[u*16+w]*e2;
        d += qki[u*16+w]*e2;
    }
    g_M[t] = a; g_M[256+t] = b; g_M[512+t] = c; g_M[768+t] = d;
}

// ---------------- quantum small path ----------------
__global__ __launch_bounds__(128) void quantum_kernel(
    const float* __restrict__ x, const float* __restrict__ sgq, const float* __restrict__ sgk)
{
    __shared__ float xs[1024];
    __shared__ float part[8][16];
    __shared__ float qss[16];
    __shared__ float prob_s[16];
    int i = blockIdx.x;
    int t = threadIdx.x;
#pragma unroll
    for (int c = 0; c < 2; c++)
        *(float4*)&xs[(t + c*128)*4] = *(const float4*)&x[(size_t)i*1024 + (t + c*128)*4];
    __syncthreads();
    int tt = t & 15, pp = t >> 4;
#pragma unroll 1
    for (int side = 0; side < 2; side++) {
        const float* sg = side ? sgk : sgq;
        float acc = 0.f;
        int base = pp * 128;
        for (int d = 0; d < 128; d++)
            acc += xs[base + d] * sg[(base + d)*16 + tt];
        part[pp][tt] = acc;
        __syncthreads();
        if (t < 16) {
            float q = 0.f;
#pragma unroll
            for (int p = 0; p < 8; p++) q += part[p][t];
            qss[t] = q;
        }
        __syncthreads();
        if (t < 16) {
            const float* Mr = g_M + side*512;
            const float* Mi = Mr + 256;
            float er = 0.f, ei = 0.f;
#pragma unroll
            for (int u = 0; u < 16; u++) {
                er += qss[u]*Mr[u*16+t];
                ei += qss[u]*Mi[u*16+t];
            }
            float pr = er*er + ei*ei;
            prob_s[t] = pr;
            (side ? g_probs_k : g_probs_q)[i*16 + t] = pr;
        }
        __syncthreads();
        if (t == 0) {
            float ms = 0.f;
#pragma unroll
            for (int u = 0; u < 16; u++) ms += prob_s[u];
            ms *= (1.f/16.f);
            (side ? g_fw_k : g_fw_q)[i] = 1.f/(1.f + __expf(-ms));
        }
        __syncthreads();
    }
}

// ---------------- combine ----------------
__global__ __launch_bounds__(256) void combine_kernel(
    const float* __restrict__ qq_mb, const float* __restrict__ qk_mb)
{
    int i = blockIdx.x;
    int b = i >> 11, s = i & 2047;
    int t = threadIdx.x;
    __shared__ float pqs[16], pks[16];
    if (t < 16) pqs[t] = g_probs_q[i*16 + t];
    else if (t < 32) pks[t-16] = g_probs_k[i*16 + (t-16)];
    __syncthreads();
    float fq = g_fw_q[i], fk = g_fw_k[i];
    int d0 = t * 4;
    float4 qv = *(const float4*)&g_Q [(size_t)i*1024 + d0];
    float4 kv = *(const float4*)&g_K [(size_t)i*1024 + d0];
    float4 vv = *(const float4*)&g_V [(size_t)i*1024 + d0];
    float4 cq = *(const float4*)&g_Cq[(size_t)i*1024 + d0];
    float4 ck = *(const float4*)&g_Ck[(size_t)i*1024 + d0];
    const float* qvp = (const float*)&qv;
    const float* kvp = (const float*)&kv;
    const float* cqp = (const float*)&cq;
    const float* ckp = (const float*)&ck;
    ushort4 qh4, kh4;
    unsigned short* qhp = &qh4.x;
    unsigned short* khp = &kh4.x;
#pragma unroll
    for (int j = 0; j < 4; j++) {
        int d = d0 + j;
        float qmb = 0.f, kmb = 0.f;
#pragma unroll
        for (int u = 0; u < 16; u++) {
            qmb += pqs[u] * qq_mb[u*1024 + d];
            kmb += pks[u] * qk_mb[u*1024 + d];
        }
        float qq = fq*qmb + (1.f - fq)*cqp[j];
        float kq = fk*kmb + (1.f - fk)*ckp[j];
        float oq = (0.7f*qvp[j] + 0.3f*qq) * 0.125f;
        float ok =  0.7f*kvp[j] + 0.3f*kq;
        qhp[j] = __half_as_ushort(__float2half_rn(oq));
        khp[j] = __half_as_ushort(__float2half_rn(ok));
    }
    int h = d0 >> 6, dh = d0 & 63;
    int bh = b*16 + h;
    size_t qb = ((size_t)bh*SEQ + s)*AD + dh;
    *(ushort4*)&g_Qah[qb] = qh4;
    *(ushort4*)&g_Kah[qb] = kh4;
    *(float4*)&g_Va[((size_t)bh*SEQ + s)*HD + dh] = vv;
    int h2 = t >> 4, u = t & 15;
    int bh2 = b*16 + h2;
    size_t tb = ((size_t)bh2*SEQ + s)*AD + 64 + u;
    g_Qah[tb] = __float2half_rn(0.1f * pqs[u]);
    g_Kah[tb] = __float2half_rn(pks[u]);
}

// ---------------- V transpose ----------------
__global__ __launch_bounds__(256) void vtrans_kernel()
{
    __shared__ float tile[64][65];
    int s0 = blockIdx.x * 64, bh = blockIdx.y;
    int t = threadIdx.x;
    int r = t >> 2, c4 = (t & 3) * 16;
    const float* src = g_Va + ((size_t)bh*SEQ + s0 + r)*HD + c4;
#pragma unroll
    for (int j = 0; j < 16; j += 4) {
        float4 v = *(const float4*)&src[j];
        tile[r][c4 + j + 0] = v.x;
        tile[r][c4 + j + 1] = v.y;
        tile[r][c4 + j + 2] = v.z;
        tile[r][c4 + j + 3] = v.w;
    }
    __syncthreads();
    int d = t >> 2, sc = (t & 3) * 16;
    ushort4 ho[4];
#pragma unroll
    for (int j = 0; j < 16; j++) {
        float v = tile[sc + j][d];
        (&ho[j >> 2].x)[j & 3] = __half_as_ushort(__float2half_rn(v));
    }
    size_t base = ((size_t)bh*HD + d)*SEQ + s0 + sc;
#pragma unroll
    for (int j = 0; j < 4; j++)
        *(ushort4*)&g_Vth[base + j*4] = ho[j];
}

// ---------------- flash phase 1: att + m + l ----------------
// smem: Q[64][88] at 0 (11264B); stage s: K[64][88](11264) V[64][72](9216); 3 stages.
#define FST0 11264
#define FVOFF 11264
#define FSTAGE 20480
#define FLASH2_SMEM (11264 + 3*FSTAGE)   // 72704

__device__ __forceinline__ void load_q_f(uint32_t sb, int t, int bh, int qt)
{
    const char* qh = (const char*)(g_Qah + ((size_t)bh*SEQ + qt*64)*AD);
#pragma unroll 1
    for (int i = t; i < 640; i += 128) {
        int row = i / 10, c = i % 10;
        cp16(sb + (uint32_t)(row*176 + c*16), qh + (size_t)row*160 + c*16);
    }
}

__device__ __forceinline__ void load_kv_f(uint32_t stb, int t, int bh, int k0)
{
    const char* kh = (const char*)(g_Kah + ((size_t)bh*SEQ + k0)*AD);
#pragma unroll 1
    for (int i = t; i < 640; i += 128) {
        int row = i / 10, c = i % 10;
        cp16(stb + (uint32_t)(row*176 + c*16), kh + (size_t)row*160 + c*16);
    }
    const __half* vh = g_Vth + (size_t)bh*HD*SEQ + k0;
#pragma unroll 1
    for (int i = t; i < 512; i += 128) {
        int d = i >> 3, c = i & 7;
        cp16(stb + FVOFF + (uint32_t)(d*144 + c*16), (const char*)(vh + (size_t)d*SEQ) + c*16);
    }
    asm volatile("cp.async.commit_group;\n" ::: "memory");
}

__global__ __launch_bounds__(128, 3) void flash_mma_kernel()
{
    extern __shared__ char smem[];
    uint32_t sb = smem_u32(smem);

    int qt = blockIdx.x, bh = blockIdx.y;
    int t = threadIdx.x;
    int wp = t >> 5, lane = t & 31;

    int aq = lane >> 3;
    int arow = (aq & 1) * 8 + (lane & 7);
    int akoff = (aq >> 1) * 8;
    int b4n = (lane >> 4) * 8 + (lane & 7);
    int b4k = ((lane >> 3) & 1) * 8;
    int rin = lane >> 2, cin = (lane & 3) * 2;

    load_q_f(sb, t, bh, qt);
    load_kv_f(sb + FST0, t, bh, 0);      // Q joins this commit group
    load_kv_f(sb + FST0 + FSTAGE, t, bh, 64);

    float m_run0 = -1e30f, m_run1 = -1e30f;
    float l_run0 = 0.f, l_run1 = 0.f;
    float O[8][4];
#pragma unroll
    for (int a = 0; a < 8; a++)
#pragma unroll
        for (int b = 0; b < 4; b++) O[a][b] = 0.f;
    uint32_t qf[5][4];

    int r0 = wp*16 + rin;

#pragma unroll 1
    for (int kt = 0; kt < 32; kt++) {
        if (kt < 31) asm volatile("cp.async.wait_group 1;\n" ::: "memory");
        else         asm volatile("cp.async.wait_group 0;\n" ::: "memory");
        __syncthreads();
        if (kt + 2 < 32)
            load_kv_f(sb + FST0 + (uint32_t)(((kt + 2) % 3) * FSTAGE), t, bh, (kt + 2) * 64);
        uint32_t st = sb + FST0 + (uint32_t)((kt % 3) * FSTAGE);

        if (kt == 0) {
#pragma unroll
            for (int ks = 0; ks < 5; ks++)
                ldsm4(qf[ks], sb + (uint32_t)(((wp*16 + arow)*88 + ks*16 + akoff) * 2));
        }

        float sacc[8][4];
#pragma unroll
        for (int a = 0; a < 8; a++)
#pragma unroll
            for (int b = 0; b < 4; b++) sacc[a][b] = 0.f;
#pragma unroll
        for (int ks = 0; ks < 5; ks++) {
            int kb = ks * 16;
#pragma unroll
            for (int p = 0; p < 4; p++) {
                uint32_t kaddr = st + (uint32_t)(((p*16 + b4n)*88 + kb + b4k) * 2);
                uint32_t kh4[4];
                ldsm4(kh4, kaddr);
                mma16816h(sacc[2*p],   qf[ks], kh4);
                mma16816h(sacc[2*p+1], qf[ks], kh4+2);
            }
        }

        float lm0 = -1e30f, lm1 = -1e30f;
#pragma unroll
        for (int nt = 0; nt < 8; nt++) {
            lm0 = fmaxf(lm0, fmaxf(sacc[nt][0], sacc[nt][1]));
            lm1 = fmaxf(lm1, fmaxf(sacc[nt][2], sacc[nt][3]));
        }
        lm0 = fmaxf(lm0, __shfl_xor_sync(0xffffffffu, lm0, 1));
        lm0 = fmaxf(lm0, __shfl_xor_sync(0xffffffffu, lm0, 2));
        lm1 = fmaxf(lm1, __shfl_xor_sync(0xffffffffu, lm1, 1));
        lm1 = fmaxf(lm1, __shfl_xor_sync(0xffffffffu, lm1, 2));
        float mn0 = fmaxf(m_run0, lm0);
        float mn1 = fmaxf(m_run1, lm1);
        float al0 = __expf(m_run0 - mn0);
        float al1 = __expf(m_run1 - mn1);
        m_run0 = mn0; m_run1 = mn1;

        float ls0 = 0.f, ls1 = 0.f;
#pragma unroll
        for (int nt = 0; nt < 8; nt++) {
            float p0 = __expf(sacc[nt][0] - mn0);
            float p1 = __expf(sacc[nt][1] - mn0);
            float p2 = __expf(sacc[nt][2] - mn1);
            float p3 = __expf(sacc[nt][3] - mn1);
            ls0 += p0 + p1; ls1 += p2 + p3;
            sacc[nt][0] = p0; sacc[nt][1] = p1;
            sacc[nt][2] = p2; sacc[nt][3] = p3;
        }
        ls0 += __shfl_xor_sync(0xffffffffu, ls0, 1);
        ls0 += __shfl_xor_sync(0xffffffffu, ls0, 2);
        ls1 += __shfl_xor_sync(0xffffffffu, ls1, 1);
        ls1 += __shfl_xor_sync(0xffffffffu, ls1, 2);
        l_run0 = l_run0*al0 + ls0;
        l_run1 = l_run1*al1 + ls1;
#pragma unroll
        for (int nt = 0; nt < 8; nt++) {
            O[nt][0] *= al0; O[nt][1] *= al0;
            O[nt][2] *= al1; O[nt][3] *= al1;
        }

#pragma unroll
        for (int p = 0; p < 4; p++) {
            uint32_t pf[4];
            __half2 h;
            h = __floats2half2_rn(sacc[2*p][0],   sacc[2*p][1]);   pf[0] = *(uint32_t*)&h;
            h = __floats2half2_rn(sacc[2*p][2],   sacc[2*p][3]);   pf[1] = *(uint32_t*)&h;
            h = __floats2half2_rn(sacc[2*p+1][0], sacc[2*p+1][1]); pf[2] = *(uint32_t*)&h;
            h = __floats2half2_rn(sacc[2*p+1][2], sacc[2*p+1][3]); pf[3] = *(uint32_t*)&h;
#pragma unroll
            for (int cb = 0; cb < 4; cb++) {
                uint32_t vaddr = st + FVOFF +
                    (uint32_t)(((cb*16 + b4n)*72 + p*16 + b4k) * 2);
                uint32_t vh4[4];
                ldsm4(vh4, vaddr);
                mma16816h(O[2*cb],   pf, vh4);
                mma16816h(O[2*cb+1], pf, vh4+2);
            }
        }
    }

    float inv0 = 1.f / l_run0, inv1 = 1.f / l_run1;
    int b = bh >> 4, h = bh & 15;
    int rg0 = qt*64 + r0;
#pragma unroll
    for (int j = 0; j < 8; j++) {
        int d = h*64 + j*8 + cin;
        size_t i0 = ((size_t)b*SEQ + rg0)*1024 + d;
        size_t i1 = ((size_t)b*SEQ + rg0 + 8)*1024 + d;
        *(__half2*)&g_ah[i0] = __floats2half2_rn(O[j][0]*inv0, O[j][1]*inv0);
        *(__half2*)&g_ah[i1] = __floats2half2_rn(O[j][2]*inv1, O[j][3]*inv1);
    }
    if ((lane & 3) == 0) {
        g_m[(size_t)bh*SEQ + rg0] = m_run0;
        g_l[(size_t)bh*SEQ + rg0] = l_run0;
        g_m[(size_t)bh*SEQ + rg0 + 8] = m_run1;
        g_l[(size_t)bh*SEQ + rg0 + 8] = l_run1;
    }
}

// ---------------- tail: Wo GEMM (y<8) + w-pass (y>=8) in one launch ----------------
// wpass: Q tile 128 rows (8 warps x 16), K 3-stage; smem: Q[128][88](22528) + 3x11264 = 56320
#define WQB 22528
#define WKSTG 11264
#define TAIL_SMEM GEMM_SMEM   // 61440 >= 56320

__device__ __forceinline__ void load_q_w(uint32_t sb, int t, int bh, int qt)
{
    const char* qh = (const char*)(g_Qah + ((size_t)bh*SEQ + qt*128)*AD);
#pragma unroll 1
    for (int i = t; i < 1280; i += 256) {
        int row = i / 10, c = i % 10;
        cp16(sb + (uint32_t)(row*176 + c*16), qh + (size_t)row*160 + c*16);
    }
}

__device__ __forceinline__ void load_k_w(uint32_t stb, int t, int bh, int k0)
{
    const char* kh = (const char*)(g_Kah + ((size_t)bh*SEQ + k0)*AD);
#pragma unroll 1
    for (int i = t; i < 640; i += 256) {
        int row = i / 10, c = i % 10;
        cp16(stb + (uint32_t)(row*176 + c*16), kh + (size_t)row*160 + c*16);
    }
    asm volatile("cp.async.commit_group;\n" ::: "memory");
}

__global__ __launch_bounds__(256) void tail_kernel(
    const __half* __restrict__ Ah, const __half* __restrict__ Bh,
    const float* __restrict__ bias, const float* __restrict__ resid,
    float* __restrict__ res_out, float* __restrict__ w_out)
{
    extern __shared__ char smem[];
    uint32_t sb = smem_u32(smem);

    if (blockIdx.y < 8) {
        gemm_body(sb, blockIdx.x * 128, blockIdx.y * 128,
                  Ah, Bh, bias, resid, res_out, 0);
        return;
    }

    // ---- w-pass ----
    int bh = blockIdx.x, qt = blockIdx.y - 8;   // qt in 0..15 (128-row tiles)
    int t = threadIdx.x;
    int wp = t >> 5, lane = t & 31;

    int aq = lane >> 3;
    int arow = (aq & 1) * 8 + (lane & 7);
    int akoff = (aq >> 1) * 8;
    int b4n = (lane >> 4) * 8 + (lane & 7);
    int b4k = ((lane >> 3) & 1) * 8;
    int rin = lane >> 2, cin = (lane & 3) * 2;

    load_q_w(sb, t, bh, qt);
    load_k_w(sb + WQB, t, bh, 0);       // Q joins group 0
    load_k_w(sb + WQB + WKSTG, t, bh, 64);

    int r0 = wp*16 + rin;
    float m0v = g_m[(size_t)bh*SEQ + qt*128 + r0];
    float m1v = g_m[(size_t)bh*SEQ + qt*128 + r0 + 8];
    float li0 = 1.f / g_l[(size_t)bh*SEQ + qt*128 + r0];
    float li1 = 1.f / g_l[(size_t)bh*SEQ + qt*128 + r0 + 8];
    uint32_t qf[5][4];

#pragma unroll 1
    for (int kt = 0; kt < 32; kt++) {
        if (kt < 31) asm volatile("cp.async.wait_group 1;\n" ::: "memory");
        else         asm volatile("cp.async.wait_group 0;\n" ::: "memory");
        __syncthreads();
        if (kt + 2 < 32)
            load_k_w(sb + WQB + (uint32_t)(((kt + 2) % 3) * WKSTG), t, bh, (kt + 2) * 64);
        uint32_t st = sb + WQB + (uint32_t)((kt % 3) * WKSTG);

        if (kt == 0) {
#pragma unroll
            for (int ks = 0; ks < 5; ks++)
                ldsm4(qf[ks], sb + (uint32_t)(((wp*16 + arow)*88 + ks*16 + akoff) * 2));
        }

        float sacc[8][4];
#pragma unroll
        for (int a = 0; a < 8; a++)
#pragma unroll
            for (int b = 0; b < 4; b++) sacc[a][b] = 0.f;
#pragma unroll
        for (int ks = 0; ks < 5; ks++) {
            int kb = ks * 16;
#pragma unroll
            for (int p = 0; p < 4; p++) {
                uint32_t kaddr = st + (uint32_t)(((p*16 + b4n)*88 + kb + b4k) * 2);
                uint32_t kh4[4];
                ldsm4(kh4, kaddr);
                mma16816h(sacc[2*p],   qf[ks], kh4);
                mma16816h(sacc[2*p+1], qf[ks], kh4+2);
            }
        }

        size_t wrow0 = ((size_t)bh*SEQ + qt*128 + r0) * SEQ + (size_t)kt*64 + cin;
        size_t wrow1 = wrow0 + (size_t)8 * SEQ;
#pragma unroll
        for (int nt = 0; nt < 8; nt++) {
            float p0 = __expf(sacc[nt][0] - m0v) * li0;
            float p1 = __expf(sacc[nt][1] - m0v) * li0;
            float p2 = __expf(sacc[nt][2] - m1v) * li1;
            float p3 = __expf(sacc[nt][3] - m1v) * li1;
            stcs2(&w_out[wrow0 + nt*8], p0, p1);
            stcs2(&w_out[wrow1 + nt*8], p2, p3);
        }
    }
}

// ---------------- layernorm ----------------
__global__ __launch_bounds__(256) void ln_kernel(const float* __restrict__ gam,
    const float* __restrict__ bet, float* __restrict__ y)
{
    int i = blockIdx.x, t = threadIdx.x;
    float4 v = *(const float4*)&g_res[(size_t)i*1024 + t*4];
    float s  = v.x + v.y + v.z + v.w;
    float ss = v.x*v.x + v.y*v.y + v.z*v.z + v.w*v.w;
#pragma unroll
    for (int off = 16; off; off >>= 1) {
        s  += __shfl_xor_sync(0xffffffffu, s,  off);
        ss += __shfl_xor_sync(0xffffffffu, ss, off);
    }
    __shared__ float as[8], ass[8];
    if ((t & 31) == 0) { as[t >> 5] = s; ass[t >> 5] = ss; }
    __syncthreads();
    float S = 0.f, SS = 0.f;
#pragma unroll
    for (int u = 0; u < 8; u++) { S += as[u]; SS += ass[u]; }
    float mu  = S * (1.f/1024.f);
    float var = SS * (1.f/1024.f) - mu*mu;
    float inv = rsqrtf(var + 1e-5f);
    float4 gg = *(const float4*)&gam[t*4];
    float4 bb = *(const float4*)&bet[t*4];
    float4 o;
    o.x = (v.x - mu)*inv*gg.x + bb.x;
    o.y = (v.y - mu)*inv*gg.y + bb.y;
    o.z = (v.z - mu)*inv*gg.z + bb.z;
    o.w = (v.w - mu)*inv*gg.w + bb.w;
    *(float4*)&y[(size_t)i*1024 + t*4] = o;
}

// ---------------- launch ----------------
extern "C" void kernel_launch(void* const* d_in, const int* in_sizes, int n_in,
                              void* d_out, int out_size)
{
    const float* x       = (const float*)d_in[0];
    const float* Wq      = (const float*)d_in[1];
    const float* bq      = (const float*)d_in[2];
    const float* Wk      = (const float*)d_in[3];
    const float* bk      = (const float*)d_in[4];
    const float* Wv      = (const float*)d_in[5];
    const float* bv      = (const float*)d_in[6];
    const float* Wo      = (const float*)d_in[7];
    const float* bo      = (const float*)d_in[8];
    const float* ln_g    = (const float*)d_in[9];
    const float* ln_b    = (const float*)d_in[10];
    const float* qq_W    = (const float*)d_in[11];
    const float* qq_b    = (const float*)d_in[12];
    const float* qq_qw_r = (const float*)d_in[13];
    const float* qq_qw_i = (const float*)d_in[14];
    const float* qq_sg   = (const float*)d_in[15];
    const float* qq_em   = (const float*)d_in[16];
    const float* qq_mb   = (const float*)d_in[17];
    const float* qk_W    = (const float*)d_in[18];
    const float* qk_b    = (const float*)d_in[19];
    const float* qk_qw_r = (const float*)d_in[20];
    const float* qk_qw_i = (const float*)d_in[21];
    const float* qk_sg   = (const float*)d_in[22];
    const float* qk_em   = (const float*)d_in[23];
    const float* qk_mb   = (const float*)d_in[24];

    float* y = (float*)d_out;
    float* w = y + (size_t)MROWS*DMODEL;

    float *pQ, *pK, *pV, *pCq, *pCk, *pRes;
    cudaGetSymbolAddress((void**)&pQ,   g_Q);
    cudaGetSymbolAddress((void**)&pK,   g_K);
    cudaGetSymbolAddress((void**)&pV,   g_V);
    cudaGetSymbolAddress((void**)&pCq,  g_Cq);
    cudaGetSymbolAddress((void**)&pCk,  g_Ck);
    cudaGetSymbolAddress((void**)&pRes, g_res);
    __half *pXh, *pAh, *pWh;
    cudaGetSymbolAddress((void**)&pXh, g_xh);
    cudaGetSymbolAddress((void**)&pAh, g_ah);
    cudaGetSymbolAddress((void**)&pWh, g_Wh);

    cudaFuncSetAttribute(mma_gemm5_kernel,
        cudaFuncAttributeMaxDynamicSharedMemorySize, GEMM_SMEM);
    cudaFuncSetAttribute(tail_kernel,
        cudaFuncAttributeMaxDynamicSharedMemorySize, TAIL_SMEM);
    cudaFuncSetAttribute(flash_mma_kernel,
        cudaFuncAttributeMaxDynamicSharedMemorySize, FLASH2_SMEM);

    prep_m_kernel<<<1, 256>>>(qq_qw_r, qq_qw_i, qk_qw_r, qk_qw_i, qq_em, qk_em);
    quantum_kernel<<<MROWS, 128>>>(x, qq_sg, qk_sg);

    aconv_kernel<<<MROWS*DMODEL/(256*8), 256>>>(x, pXh);
    WconvP WP;
    WP.W[0] = Wq; WP.W[1] = Wk; WP.W[2] = Wv;
    WP.W[3] = qq_W; WP.W[4] = qk_W; WP.W[5] = Wo;
    wconv6_kernel<<<dim3(32, 32, 6), dim3(32, 8)>>>(WP, pWh);

    const size_t WSZ = (size_t)DMODEL*DMODEL;
    GemmP5 P;
    P.Bh[0] = pWh + 0*WSZ; P.bias[0] = bq;   P.out[0] = pQ;  P.tanh_f[0] = 0;
    P.Bh[1] = pWh + 1*WSZ; P.bias[1] = bk;   P.out[1] = pK;  P.tanh_f[1] = 0;
    P.Bh[2] = pWh + 2*WSZ; P.bias[2] = bv;   P.out[2] = pV;  P.tanh_f[2] = 0;
    P.Bh[3] = pWh + 3*WSZ; P.bias[3] = qq_b; P.out[3] = pCq; P.tanh_f[3] = 1;
    P.Bh[4] = pWh + 4*WSZ; P.bias[4] = qk_b; P.out[4] = pCk; P.tanh_f[4] = 1;
    dim3 g5(32, 8, 5);
    mma_gemm5_kernel<<<g5, 256, GEMM_SMEM>>>(pXh, P);

    combine_kernel<<<MROWS, 256>>>(qq_mb, qk_mb);
    vtrans_kernel<<<dim3(32, 32), 256>>>();

    flash_mma_kernel<<<dim3(32, 32), 128, FLASH2_SMEM>>>();

    // tail: Wo GEMM (y<8) + w-pass (y>=8) concurrently
    tail_kernel<<<dim3(32, 24), 256, TAIL_SMEM>>>(pAh, pWh + 5*WSZ, bo, x, pRes, w);

    ln_kernel<<<MROWS, 256>>>(ln_g, ln_b, y);
}